// round 12
// baseline (speedup 1.0000x reference)
#include <cuda_runtime.h>
#include <cuda_fp16.h>
#include <cstdint>

// ---------------- problem constants ----------------
#define NNODES 50000
#define DHEAD  64
#define HIDN   256
#define KDIM   512
#define TILE_E 64            // edges per CTA
#define NTH    256           // 8 warps: 2 m-groups x 4 n-groups, warp tile 32x64
#define NCHUNK 16
#define BCHUNK_HALFS 8192    // 256 n * 32 k
#define ACHUNK_BYTES 4096    // 64 m * 32 k * 2B
#define BCHUNK_BYTES 16384
#define LND    (NNODES * DHEAD)

// ---------------- smem layout (bytes) ----------------
#define SM_SIDX  0                 // 64 ints
#define SM_DIDX  256
#define SM_B1    512               // 256 f each
#define SM_G     1536
#define SM_BE    2560
#define SM_W3    3584
#define SM_SSUM  4608              // [4][64] f
#define SM_SSQ   5632
#define SM_SDOT  6656
#define SM_MUS   7680              // 64 f
#define SM_RSS   7936
#define SM_ABUF  8192              // 3 x 4KB ring
#define SM_BBUF  (SM_ABUF + 3 * ACHUNK_BYTES)   // 5 x 16KB ring
#define SMEM_TOTAL (SM_BBUF + 5 * BCHUNK_BYTES) // 102400 -> 2 CTAs/SM (200KB)

// W1 pre-packed: per chunk, per (n-tile group, lane): uint4 = {kt0.b0, kt0.b1, kt1.b0, kt1.b1}
__device__ __half g_Bpack[NCHUNK * BCHUNK_HALFS];   // 256 KB
// Pre-activated node features: tanh(h_all[l] * imp_l) in fp16, [L][N*D]
__device__ __half g_hpack[4 * LND];                 // 25.6 MB

// ---------------- helpers ----------------
__device__ __forceinline__ uint32_t smem_u32(const void* p) {
    uint32_t a;
    asm("{ .reg .u64 t; cvta.to.shared.u64 t, %1; cvt.u32.u64 %0, t; }" : "=r"(a) : "l"(p));
    return a;
}
__device__ __forceinline__ float tanh_fast(float x) {
    float r;
    asm("tanh.approx.f32 %0, %1;" : "=f"(r) : "f"(x));
    return r;
}
__device__ __forceinline__ void cp16(uint32_t dst, const void* src) {
    asm volatile("cp.async.ca.shared.global [%0], [%1], 16;" :: "r"(dst), "l"(src));
}
__device__ __forceinline__ void cp_commit() {
    asm volatile("cp.async.commit_group;" ::: "memory");
}
template <int N>
__device__ __forceinline__ void cp_wait() {
    asm volatile("cp.async.wait_group %0;" :: "n"(N) : "memory");
}
__device__ __forceinline__ void mma_f16(float* c, const uint4& a, uint32_t b0, uint32_t b1) {
    asm volatile(
        "mma.sync.aligned.m16n8k16.row.col.f32.f16.f16.f32 "
        "{%0,%1,%2,%3}, {%4,%5,%6,%7}, {%8,%9}, {%0,%1,%2,%3};"
        : "+f"(c[0]), "+f"(c[1]), "+f"(c[2]), "+f"(c[3])
        : "r"(a.x), "r"(a.y), "r"(a.z), "r"(a.w), "r"(b0), "r"(b1));
}

// ---------------- prep 1: W1 -> fp16 uint4-per-lane fragment pack ----------------
__global__ void prep_w1(const float* __restrict__ W1) {
    int i = blockIdx.x * blockDim.x + threadIdx.x;
    if (i >= HIDN * KDIM) return;
    int n = i >> 9;
    int k = i & 511;
    int c = k >> 5, kc = k & 31;
    int kt = kc >> 4, kk = kc & 15;
    int gg = ((n >> 6) << 3) | ((n >> 3) & 7);
    int lane = ((n & 7) << 2) | ((kk >> 1) & 3);
    int breg = kk >> 3, lo = kk & 1;
    int idx = c * BCHUNK_HALFS + ((gg * 32 + lane) << 3) + ((kt * 2 + breg) << 1) + lo;
    g_Bpack[idx] = __float2half(W1[i]);
}

// ---------------- prep 2: h_all -> tanh(h*imp) fp16 ----------------
__global__ void prep_h(const float* __restrict__ h_all) {
    const int l = blockIdx.y;
    const float im = 0.1f * (float)(l + 1);
    int i4 = blockIdx.x * blockDim.x + threadIdx.x;
    if (i4 >= LND / 4) return;
    float4 v = *(const float4*)(h_all + (size_t)l * LND + i4 * 4);
    __half2 a = __floats2half2_rn(tanh_fast(v.x * im), tanh_fast(v.y * im));
    __half2 b = __floats2half2_rn(tanh_fast(v.z * im), tanh_fast(v.w * im));
    uint2 u = {*(uint32_t*)&a, *(uint32_t*)&b};
    *(uint2*)(g_hpack + (size_t)l * LND + i4 * 4) = u;
}

// ---------------- fused kernel ----------------
__global__ __launch_bounds__(NTH, 2)
void fused_edge_mlp_f16(const int*   __restrict__ src,
                        const int*   __restrict__ dst,
                        const float* __restrict__ b1,
                        const float* __restrict__ W3,
                        const float* __restrict__ b3,
                        const float* __restrict__ gamma2,
                        const float* __restrict__ beta2,
                        float* __restrict__ out,
                        int E) {
    extern __shared__ char smem[];
    const uint32_t sb = smem_u32(smem);

    const int tid  = threadIdx.x;
    const int wid  = tid >> 5;
    const int lane = tid & 31;
    const int mg   = wid >> 2;
    const int ng   = wid & 3;
    const int e_base = blockIdx.x * TILE_E;

    int*   sidx = (int*)(smem + SM_SIDX);
    int*   didx = (int*)(smem + SM_DIDX);
    float* b1s  = (float*)(smem + SM_B1);
    float* gs   = (float*)(smem + SM_G);
    float* bes  = (float*)(smem + SM_BE);
    float* w3s  = (float*)(smem + SM_W3);
    float* ssum = (float*)(smem + SM_SSUM);
    float* ssq  = (float*)(smem + SM_SSQ);
    float* sdot = (float*)(smem + SM_SDOT);
    float* mus  = (float*)(smem + SM_MUS);
    float* rss  = (float*)(smem + SM_RSS);

    // B stages 0..2 in flight ASAP (3 commit groups)
    #pragma unroll
    for (int s = 0; s < 3; ++s) {
        const __half* bsrc = g_Bpack + s * BCHUNK_HALFS;
        #pragma unroll
        for (int i = 0; i < 4; ++i)
            cp16(sb + SM_BBUF + s * BCHUNK_BYTES + (i * NTH + tid) * 16,
                 bsrc + (i * NTH + tid) * 8);
        cp_commit();
    }

    if (tid < TILE_E) {
        int eg = e_base + tid;
        if (eg >= E) eg = E - 1;
        sidx[tid] = src[eg];
        didx[tid] = dst[eg];
    }
    if (tid < HIDN) {
        b1s[tid] = b1[tid];
        gs[tid]  = gamma2[tid];
        bes[tid] = beta2[tid];
        w3s[tid] = W3[tid];
    }
    __syncthreads();

    // ---- per-thread invariant addressing ----
    const int e0 = tid >> 3;        // edge row for i=0 (i=1 -> e0+32)
    const int q  = tid & 7;         // 4-k slot within 32-k chunk
    uint32_t aoff[2][2];
    {
        const int mt = (e0 >> 4) & 1;
        const int r  = e0 & 15;
        #pragma unroll
        for (int i = 0; i < 2; ++i)
            #pragma unroll
            for (int p = 0; p < 2; ++p) {
                int kcp = 4 * q + 2 * p;
                int kt = kcp >> 4, kk = kcp & 15;
                int ln = ((r & 7) << 2) | ((kk >> 1) & 3);
                int areg = (r >> 3) | ((kk >> 3) << 1);
                aoff[i][p] = (uint32_t)(((((i * 2 + mt) * 2 + kt) * 32 + ln) * 4 + areg) * 4);
            }
    }

    float acc[2][8][4];
    #pragma unroll
    for (int mt = 0; mt < 2; ++mt)
        #pragma unroll
        for (int nt = 0; nt < 8; ++nt)
            #pragma unroll
            for (int j = 0; j < 4; ++j) acc[mt][nt][j] = 0.f;

    // gather chunk 0, STS into A slot 0 (published by iter 0's sync)
    uint2 ph[2];
    #pragma unroll
    for (int i = 0; i < 2; ++i) {
        int nidx = sidx[e0 + i * 32];
        ph[i] = *(const uint2*)(g_hpack + (size_t)nidx * DHEAD + q * 4);
    }
    #pragma unroll
    for (int i = 0; i < 2; ++i) {
        *(uint32_t*)(smem + SM_ABUF + aoff[i][0]) = ph[i].x;
        *(uint32_t*)(smem + SM_ABUF + aoff[i][1]) = ph[i].y;
    }
    // gather chunk 1 -> ph
    #pragma unroll
    for (int i = 0; i < 2; ++i) {
        int nidx = sidx[e0 + i * 32];
        ph[i] = *(const uint2*)(g_hpack + (size_t)nidx * DHEAD + 32 + q * 4);
    }

    uint4 aa[2][2];   // A fragments for current chunk (prefetched across barrier)

    #pragma unroll 1
    for (int c = 0; c < NCHUNK; ++c) {
        // B(c) own-landed by previous iteration's wait (or here); keep 1 group slack
        if (c < NCHUNK - 1) cp_wait<1>(); else cp_wait<0>();

        // issue B(c+3) into slot (c+3)%5 — pre-sync is safe: laggards read >= B(c-1)
        if (c < NCHUNK - 3) {
            const int s = (c + 3) % 5;
            const __half* bsrc = g_Bpack + (c + 3) * BCHUNK_HALFS;
            #pragma unroll
            for (int i = 0; i < 4; ++i)
                cp16(sb + SM_BBUF + s * BCHUNK_BYTES + (i * NTH + tid) * 16,
                     bsrc + (i * NTH + tid) * 8);
            cp_commit();
        }

        // STS A(c+1) into slot (c+1)%3 pre-sync (laggards read slots c%3 / (c-1)%3? only c%3)
        if (c < NCHUNK - 1) {
            char* ab = smem + SM_ABUF + ((c + 1) % 3) * ACHUNK_BYTES;
            #pragma unroll
            for (int i = 0; i < 2; ++i) {
                *(uint32_t*)(ab + aoff[i][0]) = ph[i].x;
                *(uint32_t*)(ab + aoff[i][1]) = ph[i].y;
            }
        }

        __syncthreads();   // publishes B(c) (+B(c+1) usually) and A(c+1); A(c) from prior iter

        // gather A(c+2) -> ph (LDG latency hidden under MMA)
        if (c < NCHUNK - 2) {
            const int cn = c + 2;
            const int l = cn >> 2, half = (cn >> 1) & 1, cc0 = (cn & 1) * 32;
            const int* ip = half ? didx : sidx;
            const __half* hb = g_hpack + (size_t)l * LND + cc0;
            #pragma unroll
            for (int i = 0; i < 2; ++i) {
                int nidx = ip[e0 + i * 32];
                ph[i] = *(const uint2*)(hb + (size_t)nidx * DHEAD + q * 4);
            }
        }

        // ---- MMA on chunk c ----
        {
            const uint4* Bb = (const uint4*)(smem + SM_BBUF + (c % 5) * BCHUNK_BYTES);
            if (c == 0) {
                const uint4* Ab = (const uint4*)(smem + SM_ABUF);
                #pragma unroll
                for (int mt = 0; mt < 2; ++mt)
                    #pragma unroll
                    for (int kt = 0; kt < 2; ++kt)
                        aa[mt][kt] = Ab[((mg * 2 + mt) * 2 + kt) * 32 + lane];
            }
            #pragma unroll
            for (int h = 0; h < 2; ++h) {
                uint4 bb[4];
                #pragma unroll
                for (int n4 = 0; n4 < 4; ++n4)
                    bb[n4] = Bb[(ng * 8 + h * 4 + n4) * 32 + lane];
                #pragma unroll
                for (int kt = 0; kt < 2; ++kt)
                    #pragma unroll
                    for (int mt = 0; mt < 2; ++mt)
                        #pragma unroll
                        for (int n4 = 0; n4 < 4; ++n4)
                            mma_f16(acc[mt][h * 4 + n4], aa[mt][kt],
                                    kt ? bb[n4].z : bb[n4].x,
                                    kt ? bb[n4].w : bb[n4].y);
            }
            // prefetch A fragments for chunk c+1 (published at this iter's sync)
            if (c < NCHUNK - 1) {
                const uint4* Abn = (const uint4*)(smem + SM_ABUF + ((c + 1) % 3) * ACHUNK_BYTES);
                #pragma unroll
                for (int mt = 0; mt < 2; ++mt)
                    #pragma unroll
                    for (int kt = 0; kt < 2; ++kt)
                        aa[mt][kt] = Abn[((mg * 2 + mt) * 2 + kt) * 32 + lane];
            }
        }
    }

    // ---------------- epilogue ----------------
    const int qr = lane >> 2;
    const int ql = lane & 3;

    float sums[2][2] = {{0.f, 0.f}, {0.f, 0.f}};
    float sqs[2][2]  = {{0.f, 0.f}, {0.f, 0.f}};
    #pragma unroll
    for (int mt = 0; mt < 2; ++mt) {
        #pragma unroll
        for (int nt = 0; nt < 8; ++nt) {
            int colb = ng * 64 + nt * 8 + ql * 2;
            float b10 = b1s[colb], b11 = b1s[colb + 1];
            float v0 = acc[mt][nt][0] + b10;
            float v1 = acc[mt][nt][1] + b11;
            float v2 = acc[mt][nt][2] + b10;
            float v3 = acc[mt][nt][3] + b11;
            acc[mt][nt][0] = v0; acc[mt][nt][1] = v1;
            acc[mt][nt][2] = v2; acc[mt][nt][3] = v3;
            sums[mt][0] += v0 + v1;           sums[mt][1] += v2 + v3;
            sqs[mt][0] = fmaf(v0, v0, sqs[mt][0]); sqs[mt][0] = fmaf(v1, v1, sqs[mt][0]);
            sqs[mt][1] = fmaf(v2, v2, sqs[mt][1]); sqs[mt][1] = fmaf(v3, v3, sqs[mt][1]);
        }
    }
    #pragma unroll
    for (int off = 1; off <= 2; off <<= 1) {
        #pragma unroll
        for (int mt = 0; mt < 2; ++mt)
            #pragma unroll
            for (int ro = 0; ro < 2; ++ro) {
                sums[mt][ro] += __shfl_xor_sync(0xffffffffu, sums[mt][ro], off);
                sqs[mt][ro]  += __shfl_xor_sync(0xffffffffu, sqs[mt][ro], off);
            }
    }
    if (ql == 0) {
        #pragma unroll
        for (int mt = 0; mt < 2; ++mt)
            #pragma unroll
            for (int ro = 0; ro < 2; ++ro) {
                int row = mg * 32 + mt * 16 + ro * 8 + qr;
                ssum[ng * 64 + row] = sums[mt][ro];
                ssq[ng * 64 + row]  = sqs[mt][ro];
            }
    }
    __syncthreads();

    if (tid < TILE_E) {
        float ts = ssum[tid] + ssum[64 + tid] + ssum[128 + tid] + ssum[192 + tid];
        float tq = ssq[tid]  + ssq[64 + tid]  + ssq[128 + tid]  + ssq[192 + tid];
        float mu  = ts * (1.f / 256.f);
        float var = tq * (1.f / 256.f) - mu * mu;
        mus[tid] = mu;
        rss[tid] = rsqrtf(var + 1e-5f);
    }
    __syncthreads();

    float dots[2][2] = {{0.f, 0.f}, {0.f, 0.f}};
    #pragma unroll
    for (int mt = 0; mt < 2; ++mt) {
        int row0 = mg * 32 + mt * 16 + qr;
        float mu0 = mus[row0],     rs0 = rss[row0];
        float mu1 = mus[row0 + 8], rs1 = rss[row0 + 8];
        #pragma unroll
        for (int nt = 0; nt < 8; ++nt) {
            int colb = ng * 64 + nt * 8 + ql * 2;
            float g0 = gs[colb], g1 = gs[colb + 1];
            float e0c = bes[colb], e1c = bes[colb + 1];
            float w0 = w3s[colb], w1 = w3s[colb + 1];
            float y;
            y = fmaxf((acc[mt][nt][0] - mu0) * rs0 * g0 + e0c, 0.f); dots[mt][0] = fmaf(y, w0, dots[mt][0]);
            y = fmaxf((acc[mt][nt][1] - mu0) * rs0 * g1 + e1c, 0.f); dots[mt][0] = fmaf(y, w1, dots[mt][0]);
            y = fmaxf((acc[mt][nt][2] - mu1) * rs1 * g0 + e0c, 0.f); dots[mt][1] = fmaf(y, w0, dots[mt][1]);
            y = fmaxf((acc[mt][nt][3] - mu1) * rs1 * g1 + e1c, 0.f); dots[mt][1] = fmaf(y, w1, dots[mt][1]);
        }
    }
    #pragma unroll
    for (int off = 1; off <= 2; off <<= 1)
        #pragma unroll
        for (int mt = 0; mt < 2; ++mt)
            #pragma unroll
            for (int ro = 0; ro < 2; ++ro)
                dots[mt][ro] += __shfl_xor_sync(0xffffffffu, dots[mt][ro], off);
    if (ql == 0) {
        #pragma unroll
        for (int mt = 0; mt < 2; ++mt)
            #pragma unroll
            for (int ro = 0; ro < 2; ++ro) {
                int row = mg * 32 + mt * 16 + ro * 8 + qr;
                sdot[ng * 64 + row] = dots[mt][ro];
            }
    }
    __syncthreads();

    if (tid < TILE_E) {
        int eg = e_base + tid;
        if (eg < E) {
            out[eg] = sdot[tid] + sdot[64 + tid] + sdot[128 + tid] + sdot[192 + tid] + b3[0];
        }
    }
}

extern "C" void kernel_launch(void* const* d_in, const int* in_sizes, int n_in,
                              void* d_out, int out_size) {
    const float* h_all  = (const float*)d_in[0];
    const int*   src    = (const int*)  d_in[1];
    const int*   dst    = (const int*)  d_in[2];
    const float* W1     = (const float*)d_in[3];
    const float* b1     = (const float*)d_in[4];
    const float* W3     = (const float*)d_in[5];
    const float* b3     = (const float*)d_in[6];
    const float* gamma2 = (const float*)d_in[7];
    const float* beta2  = (const float*)d_in[8];
    float* out = (float*)d_out;

    const int E = in_sizes[1];

    cudaFuncSetAttribute(fused_edge_mlp_f16,
                         cudaFuncAttributeMaxDynamicSharedMemorySize, SMEM_TOTAL);

    prep_w1<<<(HIDN * KDIM + 255) / 256, 256>>>(W1);
    {
        dim3 g((LND / 4 + 255) / 256, 4);
        prep_h<<<g, 256>>>(h_all);
    }

    int nb = (E + TILE_E - 1) / TILE_E;
    fused_edge_mlp_f16<<<nb, NTH, SMEM_TOTAL>>>(
        src, dst, b1, W3, b3, gamma2, beta2, out, E);
}

// round 13
// speedup vs baseline: 3.0638x; 3.0638x over previous
#include <cuda_runtime.h>
#include <cuda_fp16.h>
#include <cstdint>

// ---------------- problem constants ----------------
#define NNODES 50000
#define DHEAD  64
#define HIDN   256
#define KDIM   512
#define KNODE  256           // per-node feature count (L*D)
#define TILE_M 64            // nodes per CTA (node GEMM)
#define NTH    256           // 8 warps: 2 m-groups x 4 n-groups, warp tile 32x64
#define NCHUNK 8             // K=256 / 32
#define BCHUNK_HALFS 8192    // 256 n * 32 k
#define ACHUNK_BYTES 4096    // 64 m * 32 k * 2B
#define BCHUNK_BYTES 16384
#define LND    (NNODES * DHEAD)

// ---------------- node-GEMM smem layout (bytes) ----------------
#define SM_B1    0                 // 256 f
#define SM_ABUF  1024              // 3 x 4KB ring
#define SM_BBUF  (SM_ABUF + 3 * ACHUNK_BYTES)   // 3 x 16KB ring
#define SMEM_TOTAL (SM_BBUF + 3 * BCHUNK_BYTES) // 62464 -> 2 CTAs/SM

// ---------------- device globals ----------------
// pre-activated node features: tanh(h_all[l]*imp_l) fp16, [L][N*D]
__device__ __half g_hpack[4 * LND];                   // 25.6 MB
// W1 split-halves, fragment-packed per 32-k chunk: [half][chunk][8192]
__device__ __half g_BpackN[2 * NCHUNK * BCHUNK_HALFS];// 256 KB
// per-node projections (fp16): y_s includes b1
__device__ __half g_ys[(size_t)NNODES * HIDN];        // 25.6 MB
__device__ __half g_yd[(size_t)NNODES * HIDN];        // 25.6 MB

// ---------------- helpers ----------------
__device__ __forceinline__ uint32_t smem_u32(const void* p) {
    uint32_t a;
    asm("{ .reg .u64 t; cvta.to.shared.u64 t, %1; cvt.u32.u64 %0, t; }" : "=r"(a) : "l"(p));
    return a;
}
__device__ __forceinline__ float tanh_fast(float x) {
    float r;
    asm("tanh.approx.f32 %0, %1;" : "=f"(r) : "f"(x));
    return r;
}
__device__ __forceinline__ void cp16(uint32_t dst, const void* src) {
    asm volatile("cp.async.ca.shared.global [%0], [%1], 16;" :: "r"(dst), "l"(src));
}
__device__ __forceinline__ void cp_commit() {
    asm volatile("cp.async.commit_group;" ::: "memory");
}
template <int N>
__device__ __forceinline__ void cp_wait() {
    asm volatile("cp.async.wait_group %0;" :: "n"(N) : "memory");
}
__device__ __forceinline__ void mma_f16(float* c, const uint4& a, uint32_t b0, uint32_t b1) {
    asm volatile(
        "mma.sync.aligned.m16n8k16.row.col.f32.f16.f16.f32 "
        "{%0,%1,%2,%3}, {%4,%5,%6,%7}, {%8,%9}, {%0,%1,%2,%3};"
        : "+f"(c[0]), "+f"(c[1]), "+f"(c[2]), "+f"(c[3])
        : "r"(a.x), "r"(a.y), "r"(a.z), "r"(a.w), "r"(b0), "r"(b1));
}

// ---------------- prep 1: h_all -> tanh(h*imp) fp16 ----------------
__global__ void prep_h(const float* __restrict__ h_all) {
    const int l = blockIdx.y;
    const float im = 0.1f * (float)(l + 1);
    int i4 = blockIdx.x * blockDim.x + threadIdx.x;
    if (i4 >= LND / 4) return;
    float4 v = *(const float4*)(h_all + (size_t)l * LND + i4 * 4);
    __half2 a = __floats2half2_rn(tanh_fast(v.x * im), tanh_fast(v.y * im));
    __half2 b = __floats2half2_rn(tanh_fast(v.z * im), tanh_fast(v.w * im));
    uint2 u = {*(uint32_t*)&a, *(uint32_t*)&b};
    *(uint2*)(g_hpack + (size_t)l * LND + i4 * 4) = u;
}

// ---------------- prep 2: W1 src/dst halves -> fragment pack ----------------
// k' = l*64 + c maps to W1 column l*128 + half*64 + c.
__global__ void prep_w1n(const float* __restrict__ W1) {
    int i = blockIdx.x * blockDim.x + threadIdx.x;
    if (i >= 2 * HIDN * KNODE) return;
    int half = i >> 16;          // 65536 per half
    int r = i & 65535;
    int j = r >> 8;              // output col (W1 row) 0..255
    int kp = r & 255;            // k'
    int l = kp >> 6, cc = kp & 63;
    int ksrc = l * 128 + half * 64 + cc;
    int c = kp >> 5, kc = kp & 31;
    int kt = kc >> 4, kk = kc & 15;
    int gg = ((j >> 6) << 3) | ((j >> 3) & 7);
    int lane = ((j & 7) << 2) | ((kk >> 1) & 3);
    int breg = kk >> 3, lo = kk & 1;
    int idx = half * (NCHUNK * BCHUNK_HALFS) + c * BCHUNK_HALFS +
              ((gg * 32 + lane) << 3) + ((kt * 2 + breg) << 1) + lo;
    g_BpackN[idx] = __float2half(W1[j * KDIM + ksrc]);
}

// ---------------- node GEMM: y[half][node, 256] ----------------
// grid.x = node tiles, grid.y = half (0: src cols + b1, 1: dst cols)
__global__ __launch_bounds__(NTH, 2)
void node_proj(const float* __restrict__ b1) {
    extern __shared__ char smem[];
    const uint32_t sb = smem_u32(smem);

    const int tid  = threadIdx.x;
    const int wid  = tid >> 5;
    const int lane = tid & 31;
    const int mg   = wid >> 2;
    const int ng   = wid & 3;
    const int nb   = blockIdx.x * TILE_M;
    const int half = blockIdx.y;

    float* b1s = (float*)(smem + SM_B1);
    const __half* Bsrc0 = g_BpackN + (size_t)half * (NCHUNK * BCHUNK_HALFS);

    // B stages 0,1 in flight
    #pragma unroll
    for (int s = 0; s < 2; ++s) {
        const __half* bsrc = Bsrc0 + s * BCHUNK_HALFS;
        #pragma unroll
        for (int i = 0; i < 4; ++i)
            cp16(sb + SM_BBUF + s * BCHUNK_BYTES + (i * NTH + tid) * 16,
                 bsrc + (i * NTH + tid) * 8);
        cp_commit();
    }
    if (tid < HIDN) b1s[tid] = (half == 0) ? b1[tid] : 0.f;
    __syncthreads();

    // per-thread invariant addressing (validated fragment math)
    const int e0 = tid >> 3;        // row-in-tile for i=0 (i=1 -> +32)
    const int q  = tid & 7;
    uint32_t aoff[2][2];
    {
        const int mt = (e0 >> 4) & 1;
        const int r  = e0 & 15;
        #pragma unroll
        for (int i = 0; i < 2; ++i)
            #pragma unroll
            for (int p = 0; p < 2; ++p) {
                int kcp = 4 * q + 2 * p;
                int kt = kcp >> 4, kk = kcp & 15;
                int ln = ((r & 7) << 2) | ((kk >> 1) & 3);
                int areg = (r >> 3) | ((kk >> 3) << 1);
                aoff[i][p] = (uint32_t)(((((i * 2 + mt) * 2 + kt) * 32 + ln) * 4 + areg) * 4);
            }
    }
    // clamped node rows (contiguous tile)
    int nrow[2];
    #pragma unroll
    for (int i = 0; i < 2; ++i) {
        int n = nb + e0 + i * 32;
        nrow[i] = (n < NNODES) ? n : (NNODES - 1);
    }

    float acc[2][8][4];
    #pragma unroll
    for (int mt = 0; mt < 2; ++mt)
        #pragma unroll
        for (int nt = 0; nt < 8; ++nt)
            #pragma unroll
            for (int j = 0; j < 4; ++j) acc[mt][nt][j] = 0.f;

    // gather chunk 0 (l=0, cc0=0), STS, gather chunk 1
    uint2 ph[2];
    #pragma unroll
    for (int i = 0; i < 2; ++i)
        ph[i] = *(const uint2*)(g_hpack + (size_t)nrow[i] * DHEAD + q * 4);
    #pragma unroll
    for (int i = 0; i < 2; ++i) {
        *(uint32_t*)(smem + SM_ABUF + aoff[i][0]) = ph[i].x;
        *(uint32_t*)(smem + SM_ABUF + aoff[i][1]) = ph[i].y;
    }
    #pragma unroll
    for (int i = 0; i < 2; ++i)
        ph[i] = *(const uint2*)(g_hpack + (size_t)nrow[i] * DHEAD + 32 + q * 4);

    #pragma unroll 1
    for (int c = 0; c < NCHUNK; ++c) {
        if (c < NCHUNK - 1) cp_wait<1>(); else cp_wait<0>();
        __syncthreads();

        if (c < NCHUNK - 2) {
            const int s = (c + 2) % 3;
            const __half* bsrc = Bsrc0 + (c + 2) * BCHUNK_HALFS;
            #pragma unroll
            for (int i = 0; i < 4; ++i)
                cp16(sb + SM_BBUF + s * BCHUNK_BYTES + (i * NTH + tid) * 16,
                     bsrc + (i * NTH + tid) * 8);
            cp_commit();
        }
        if (c < NCHUNK - 1) {
            char* ab = smem + SM_ABUF + ((c + 1) % 3) * ACHUNK_BYTES;
            #pragma unroll
            for (int i = 0; i < 2; ++i) {
                *(uint32_t*)(ab + aoff[i][0]) = ph[i].x;
                *(uint32_t*)(ab + aoff[i][1]) = ph[i].y;
            }
        }
        if (c < NCHUNK - 2) {
            const int cn = c + 2;
            const int l = cn >> 1, cc0 = (cn & 1) * 32;
            const __half* hb = g_hpack + (size_t)l * LND + cc0;
            #pragma unroll
            for (int i = 0; i < 2; ++i)
                ph[i] = *(const uint2*)(hb + (size_t)nrow[i] * DHEAD + q * 4);
        }

        {
            const uint4* Ab = (const uint4*)(smem + SM_ABUF + (c % 3) * ACHUNK_BYTES);
            const uint4* Bb = (const uint4*)(smem + SM_BBUF + (c % 3) * BCHUNK_BYTES);
            uint4 aa[2][2];
            #pragma unroll
            for (int mt = 0; mt < 2; ++mt)
                #pragma unroll
                for (int kt = 0; kt < 2; ++kt)
                    aa[mt][kt] = Ab[((mg * 2 + mt) * 2 + kt) * 32 + lane];
            #pragma unroll
            for (int h = 0; h < 2; ++h) {
                uint4 bb[4];
                #pragma unroll
                for (int n4 = 0; n4 < 4; ++n4)
                    bb[n4] = Bb[(ng * 8 + h * 4 + n4) * 32 + lane];
                #pragma unroll
                for (int kt = 0; kt < 2; ++kt)
                    #pragma unroll
                    for (int mt = 0; mt < 2; ++mt)
                        #pragma unroll
                        for (int n4 = 0; n4 < 4; ++n4)
                            mma_f16(acc[mt][h * 4 + n4], aa[mt][kt],
                                    kt ? bb[n4].z : bb[n4].x,
                                    kt ? bb[n4].w : bb[n4].y);
            }
        }
    }

    // epilogue: +b1 (src half), fp16 store
    const int qr = lane >> 2;
    const int ql = lane & 3;
    __half* yout = half ? g_yd : g_ys;
    #pragma unroll
    for (int mt = 0; mt < 2; ++mt) {
        int row0 = nb + mg * 32 + mt * 16 + qr;
        #pragma unroll
        for (int nt = 0; nt < 8; ++nt) {
            int colb = ng * 64 + nt * 8 + ql * 2;
            float b10 = b1s[colb], b11 = b1s[colb + 1];
            if (row0 < NNODES) {
                __half2 h2 = __floats2half2_rn(acc[mt][nt][0] + b10, acc[mt][nt][1] + b11);
                *(__half2*)(yout + (size_t)row0 * HIDN + colb) = h2;
            }
            if (row0 + 8 < NNODES) {
                __half2 h2 = __floats2half2_rn(acc[mt][nt][2] + b10, acc[mt][nt][3] + b11);
                *(__half2*)(yout + (size_t)(row0 + 8) * HIDN + colb) = h2;
            }
        }
    }
}

// ---------------- edge epilogue: gather y_s+y_d, LN, ReLU, dot ----------------
// warp per 32 edges; lane owns 8 columns (lane*8 .. +7)
__global__ __launch_bounds__(NTH)
void edge_out(const int* __restrict__ src,
              const int* __restrict__ dst,
              const float* __restrict__ W3,
              const float* __restrict__ b3,
              const float* __restrict__ gamma2,
              const float* __restrict__ beta2,
              float* __restrict__ out,
              int E) {
    const int tid  = threadIdx.x;
    const int wid  = tid >> 5;
    const int lane = tid & 31;
    const int ebase = blockIdx.x * NTH + wid * 32;
    if (ebase >= E) return;

    // per-lane column params (2x float4 each)
    const int j0 = lane * 8;
    float4 ga = *(const float4*)(gamma2 + j0), gb = *(const float4*)(gamma2 + j0 + 4);
    float4 ba = *(const float4*)(beta2 + j0),  bb = *(const float4*)(beta2 + j0 + 4);
    float4 wa = *(const float4*)(W3 + j0),     wb = *(const float4*)(W3 + j0 + 4);
    const float g[8]  = {ga.x, ga.y, ga.z, ga.w, gb.x, gb.y, gb.z, gb.w};
    const float be[8] = {ba.x, ba.y, ba.z, ba.w, bb.x, bb.y, bb.z, bb.w};
    const float w3[8] = {wa.x, wa.y, wa.z, wa.w, wb.x, wb.y, wb.z, wb.w};
    const float b3v = b3[0];

    int eg = ebase + lane;
    if (eg >= E) eg = E - 1;
    const int se = src[eg], de = dst[eg];

    int s0 = __shfl_sync(0xffffffffu, se, 0);
    int d0 = __shfl_sync(0xffffffffu, de, 0);
    uint4 us = *(const uint4*)(g_ys + (size_t)s0 * HIDN + j0);
    uint4 ud = *(const uint4*)(g_yd + (size_t)d0 * HIDN + j0);

    #pragma unroll 4
    for (int t = 0; t < 32; ++t) {
        uint4 usn = us, udn = ud;
        if (t < 31) {
            int s2 = __shfl_sync(0xffffffffu, se, t + 1);
            int d2 = __shfl_sync(0xffffffffu, de, t + 1);
            usn = *(const uint4*)(g_ys + (size_t)s2 * HIDN + j0);
            udn = *(const uint4*)(g_yd + (size_t)d2 * HIDN + j0);
        }
        float x[8];
        float sum = 0.f, sq = 0.f;
        {
            const __half2* hs = (const __half2*)&us;
            const __half2* hd = (const __half2*)&ud;
            #pragma unroll
            for (int w = 0; w < 4; ++w) {
                float2 a = __half22float2(hs[w]);
                float2 b = __half22float2(hd[w]);
                x[2 * w]     = a.x + b.x;
                x[2 * w + 1] = a.y + b.y;
                sum += x[2 * w] + x[2 * w + 1];
                sq = fmaf(x[2 * w], x[2 * w], sq);
                sq = fmaf(x[2 * w + 1], x[2 * w + 1], sq);
            }
        }
        #pragma unroll
        for (int off = 16; off > 0; off >>= 1) {
            sum += __shfl_xor_sync(0xffffffffu, sum, off);
            sq  += __shfl_xor_sync(0xffffffffu, sq, off);
        }
        float mu  = sum * (1.f / 256.f);
        float var = sq * (1.f / 256.f) - mu * mu;
        float rs  = rsqrtf(var + 1e-5f);
        float p = 0.f;
        #pragma unroll
        for (int w = 0; w < 8; ++w) {
            float y = fmaxf((x[w] - mu) * rs * g[w] + be[w], 0.f);
            p = fmaf(y, w3[w], p);
        }
        #pragma unroll
        for (int off = 16; off > 0; off >>= 1)
            p += __shfl_xor_sync(0xffffffffu, p, off);
        if (lane == 0 && ebase + t < E)
            out[ebase + t] = p + b3v;
        us = usn;
        ud = udn;
    }
}

extern "C" void kernel_launch(void* const* d_in, const int* in_sizes, int n_in,
                              void* d_out, int out_size) {
    const float* h_all  = (const float*)d_in[0];
    const int*   src    = (const int*)  d_in[1];
    const int*   dst    = (const int*)  d_in[2];
    const float* W1     = (const float*)d_in[3];
    const float* b1     = (const float*)d_in[4];
    const float* W3     = (const float*)d_in[5];
    const float* b3     = (const float*)d_in[6];
    const float* gamma2 = (const float*)d_in[7];
    const float* beta2  = (const float*)d_in[8];
    float* out = (float*)d_out;

    const int E = in_sizes[1];

    cudaFuncSetAttribute(node_proj,
                         cudaFuncAttributeMaxDynamicSharedMemorySize, SMEM_TOTAL);

    {
        dim3 g((LND / 4 + 255) / 256, 4);
        prep_h<<<g, 256>>>(h_all);
    }
    prep_w1n<<<(2 * HIDN * KNODE + 255) / 256, 256>>>(W1);

    {
        dim3 g((NNODES + TILE_M - 1) / TILE_M, 2);
        node_proj<<<g, NTH, SMEM_TOTAL>>>(b1);
    }

    int nb2 = (E + NTH - 1) / NTH;
    edge_out<<<nb2, NTH>>>(src, dst, W3, b3, gamma2, beta2, out, E);
}

// round 14
// speedup vs baseline: 3.0767x; 1.0042x over previous
#include <cuda_runtime.h>
#include <cuda_fp16.h>
#include <cstdint>

// ---------------- problem constants ----------------
#define NNODES 50000
#define DHEAD  64
#define HIDN   256
#define KDIM   512
#define KNODE  256           // per-node feature count (L*D)
#define TILE_M 64            // nodes per CTA (node GEMM)
#define NTH    256
#define NCHUNK 8             // K=256 / 32
#define BCHUNK_HALFS 8192    // 256 n * 32 k
#define ACHUNK_BYTES 4096    // 64 m * 32 k * 2B
#define BCHUNK_BYTES 16384
#define LND    (NNODES * DHEAD)

// ---------------- node-GEMM smem layout (bytes) ----------------
#define SM_B1    0
#define SM_ABUF  1024              // 3 x 4KB ring
#define SM_BBUF  (SM_ABUF + 3 * ACHUNK_BYTES)   // 3 x 16KB ring
#define SMEM_TOTAL (SM_BBUF + 3 * BCHUNK_BYTES) // 62464 -> 2 CTAs/SM

// ---------------- device globals ----------------
__device__ __half g_BpackN[2 * NCHUNK * BCHUNK_HALFS];// 256 KB
__device__ __half g_ys[(size_t)NNODES * HIDN];        // 25.6 MB (includes b1)
__device__ __half g_yd[(size_t)NNODES * HIDN];        // 25.6 MB

// ---------------- helpers ----------------
__device__ __forceinline__ uint32_t smem_u32(const void* p) {
    uint32_t a;
    asm("{ .reg .u64 t; cvta.to.shared.u64 t, %1; cvt.u32.u64 %0, t; }" : "=r"(a) : "l"(p));
    return a;
}
__device__ __forceinline__ float tanh_fast(float x) {
    float r;
    asm("tanh.approx.f32 %0, %1;" : "=f"(r) : "f"(x));
    return r;
}
__device__ __forceinline__ void cp16(uint32_t dst, const void* src) {
    asm volatile("cp.async.ca.shared.global [%0], [%1], 16;" :: "r"(dst), "l"(src));
}
__device__ __forceinline__ void cp_commit() {
    asm volatile("cp.async.commit_group;" ::: "memory");
}
template <int N>
__device__ __forceinline__ void cp_wait() {
    asm volatile("cp.async.wait_group %0;" :: "n"(N) : "memory");
}
__device__ __forceinline__ void mma_f16(float* c, const uint4& a, uint32_t b0, uint32_t b1) {
    asm volatile(
        "mma.sync.aligned.m16n8k16.row.col.f32.f16.f16.f32 "
        "{%0,%1,%2,%3}, {%4,%5,%6,%7}, {%8,%9}, {%0,%1,%2,%3};"
        : "+f"(c[0]), "+f"(c[1]), "+f"(c[2]), "+f"(c[3])
        : "r"(a.x), "r"(a.y), "r"(a.z), "r"(a.w), "r"(b0), "r"(b1));
}
// packed fp32x2 (sm_100+ base ISA)
__device__ __forceinline__ unsigned long long pk2(float lo, float hi) {
    unsigned long long r;
    asm("mov.b64 %0, {%1, %2};" : "=l"(r) : "f"(lo), "f"(hi));
    return r;
}
__device__ __forceinline__ void upk2(float& lo, float& hi, unsigned long long v) {
    asm("mov.b64 {%0, %1}, %2;" : "=f"(lo), "=f"(hi) : "l"(v));
}
__device__ __forceinline__ unsigned long long addx2(unsigned long long a, unsigned long long b) {
    unsigned long long r;
    asm("add.rn.f32x2 %0, %1, %2;" : "=l"(r) : "l"(a), "l"(b));
    return r;
}
__device__ __forceinline__ unsigned long long mulx2(unsigned long long a, unsigned long long b) {
    unsigned long long r;
    asm("mul.rn.f32x2 %0, %1, %2;" : "=l"(r) : "l"(a), "l"(b));
    return r;
}
__device__ __forceinline__ unsigned long long fmax2(unsigned long long a, unsigned long long b,
                                                    unsigned long long c) {
    unsigned long long r;
    asm("fma.rn.f32x2 %0, %1, %2, %3;" : "=l"(r) : "l"(a), "l"(b), "l"(c));
    return r;
}

// ---------------- prep: W1 src/dst halves -> fragment pack ----------------
__global__ void prep_w1n(const float* __restrict__ W1) {
    int i = blockIdx.x * blockDim.x + threadIdx.x;
    if (i >= 2 * HIDN * KNODE) return;
    int half = i >> 16;
    int r = i & 65535;
    int j = r >> 8;              // output col (W1 row)
    int kp = r & 255;            // k'
    int l = kp >> 6, cc = kp & 63;
    int ksrc = l * 128 + half * 64 + cc;
    int c = kp >> 5, kc = kp & 31;
    int kt = kc >> 4, kk = kc & 15;
    int gg = ((j >> 6) << 3) | ((j >> 3) & 7);
    int lane = ((j & 7) << 2) | ((kk >> 1) & 3);
    int breg = kk >> 3, lo = kk & 1;
    int idx = half * (NCHUNK * BCHUNK_HALFS) + c * BCHUNK_HALFS +
              ((gg * 32 + lane) << 3) + ((kt * 2 + breg) << 1) + lo;
    g_BpackN[idx] = __float2half(W1[j * KDIM + ksrc]);
}

// ---------------- node GEMM: y[half][node, 256] (tanh fused in producer) ----------------
__global__ __launch_bounds__(NTH, 2)
void node_proj(const float* __restrict__ h_all, const float* __restrict__ b1) {
    extern __shared__ char smem[];
    const uint32_t sb = smem_u32(smem);

    const int tid  = threadIdx.x;
    const int wid  = tid >> 5;
    const int lane = tid & 31;
    const int mg   = wid >> 2;
    const int ng   = wid & 3;
    const int nb   = blockIdx.x * TILE_M;
    const int half = blockIdx.y;

    float* b1s = (float*)(smem + SM_B1);
    const __half* Bsrc0 = g_BpackN + (size_t)half * (NCHUNK * BCHUNK_HALFS);

    #pragma unroll
    for (int s = 0; s < 2; ++s) {
        const __half* bsrc = Bsrc0 + s * BCHUNK_HALFS;
        #pragma unroll
        for (int i = 0; i < 4; ++i)
            cp16(sb + SM_BBUF + s * BCHUNK_BYTES + (i * NTH + tid) * 16,
                 bsrc + (i * NTH + tid) * 8);
        cp_commit();
    }
    if (tid < HIDN) b1s[tid] = (half == 0) ? b1[tid] : 0.f;
    __syncthreads();

    const int e0 = tid >> 3;
    const int q  = tid & 7;
    uint32_t aoff[2][2];
    {
        const int mt = (e0 >> 4) & 1;
        const int r  = e0 & 15;
        #pragma unroll
        for (int i = 0; i < 2; ++i)
            #pragma unroll
            for (int p = 0; p < 2; ++p) {
                int kcp = 4 * q + 2 * p;
                int kt = kcp >> 4, kk = kcp & 15;
                int ln = ((r & 7) << 2) | ((kk >> 1) & 3);
                int areg = (r >> 3) | ((kk >> 3) << 1);
                aoff[i][p] = (uint32_t)(((((i * 2 + mt) * 2 + kt) * 32 + ln) * 4 + areg) * 4);
            }
    }
    int nrow[2];
    #pragma unroll
    for (int i = 0; i < 2; ++i) {
        int n = nb + e0 + i * 32;
        nrow[i] = (n < NNODES) ? n : (NNODES - 1);
    }

    float acc[2][8][4];
    #pragma unroll
    for (int mt = 0; mt < 2; ++mt)
        #pragma unroll
        for (int nt = 0; nt < 8; ++nt)
            #pragma unroll
            for (int j = 0; j < 4; ++j) acc[mt][nt][j] = 0.f;

    // producer: gather fp32 + tanh + pack (R7-proven code), chunk c: l=c>>1, cc0=(c&1)*32
    uint2 ph[2];
    #pragma unroll
    for (int i = 0; i < 2; ++i) {
        float4 v = *(const float4*)(h_all + (size_t)nrow[i] * DHEAD + q * 4);
        __half2 a = __floats2half2_rn(tanh_fast(v.x * 0.1f), tanh_fast(v.y * 0.1f));
        __half2 b = __floats2half2_rn(tanh_fast(v.z * 0.1f), tanh_fast(v.w * 0.1f));
        ph[i].x = *(uint32_t*)&a;
        ph[i].y = *(uint32_t*)&b;
    }
    #pragma unroll
    for (int i = 0; i < 2; ++i) {
        *(uint32_t*)(smem + SM_ABUF + aoff[i][0]) = ph[i].x;
        *(uint32_t*)(smem + SM_ABUF + aoff[i][1]) = ph[i].y;
    }
    #pragma unroll
    for (int i = 0; i < 2; ++i) {
        float4 v = *(const float4*)(h_all + (size_t)nrow[i] * DHEAD + 32 + q * 4);
        __half2 a = __floats2half2_rn(tanh_fast(v.x * 0.1f), tanh_fast(v.y * 0.1f));
        __half2 b = __floats2half2_rn(tanh_fast(v.z * 0.1f), tanh_fast(v.w * 0.1f));
        ph[i].x = *(uint32_t*)&a;
        ph[i].y = *(uint32_t*)&b;
    }

    #pragma unroll 1
    for (int c = 0; c < NCHUNK; ++c) {
        if (c < NCHUNK - 1) cp_wait<1>(); else cp_wait<0>();
        __syncthreads();

        if (c < NCHUNK - 2) {
            const int s = (c + 2) % 3;
            const __half* bsrc = Bsrc0 + (c + 2) * BCHUNK_HALFS;
            #pragma unroll
            for (int i = 0; i < 4; ++i)
                cp16(sb + SM_BBUF + s * BCHUNK_BYTES + (i * NTH + tid) * 16,
                     bsrc + (i * NTH + tid) * 8);
            cp_commit();
        }
        if (c < NCHUNK - 1) {
            char* ab = smem + SM_ABUF + ((c + 1) % 3) * ACHUNK_BYTES;
            #pragma unroll
            for (int i = 0; i < 2; ++i) {
                *(uint32_t*)(ab + aoff[i][0]) = ph[i].x;
                *(uint32_t*)(ab + aoff[i][1]) = ph[i].y;
            }
        }
        if (c < NCHUNK - 2) {
            const int cn = c + 2;
            const int l = cn >> 1, cc0 = (cn & 1) * 32;
            const float im = 0.1f * (float)(l + 1);
            const float* hb = h_all + (size_t)l * LND + cc0;
            #pragma unroll
            for (int i = 0; i < 2; ++i) {
                float4 v = *(const float4*)(hb + (size_t)nrow[i] * DHEAD + q * 4);
                __half2 a = __floats2half2_rn(tanh_fast(v.x * im), tanh_fast(v.y * im));
                __half2 b = __floats2half2_rn(tanh_fast(v.z * im), tanh_fast(v.w * im));
                ph[i].x = *(uint32_t*)&a;
                ph[i].y = *(uint32_t*)&b;
            }
        }

        {
            const uint4* Ab = (const uint4*)(smem + SM_ABUF + (c % 3) * ACHUNK_BYTES);
            const uint4* Bb = (const uint4*)(smem + SM_BBUF + (c % 3) * BCHUNK_BYTES);
            uint4 aa[2][2];
            #pragma unroll
            for (int mt = 0; mt < 2; ++mt)
                #pragma unroll
                for (int kt = 0; kt < 2; ++kt)
                    aa[mt][kt] = Ab[((mg * 2 + mt) * 2 + kt) * 32 + lane];
            #pragma unroll
            for (int h = 0; h < 2; ++h) {
                uint4 bb[4];
                #pragma unroll
                for (int n4 = 0; n4 < 4; ++n4)
                    bb[n4] = Bb[(ng * 8 + h * 4 + n4) * 32 + lane];
                #pragma unroll
                for (int kt = 0; kt < 2; ++kt)
                    #pragma unroll
                    for (int mt = 0; mt < 2; ++mt)
                        #pragma unroll
                        for (int n4 = 0; n4 < 4; ++n4)
                            mma_f16(acc[mt][h * 4 + n4], aa[mt][kt],
                                    kt ? bb[n4].z : bb[n4].x,
                                    kt ? bb[n4].w : bb[n4].y);
            }
        }
    }

    const int qr = lane >> 2;
    const int ql = lane & 3;
    __half* yout = half ? g_yd : g_ys;
    #pragma unroll
    for (int mt = 0; mt < 2; ++mt) {
        int row0 = nb + mg * 32 + mt * 16 + qr;
        #pragma unroll
        for (int nt = 0; nt < 8; ++nt) {
            int colb = ng * 64 + nt * 8 + ql * 2;
            float b10 = b1s[colb], b11 = b1s[colb + 1];
            if (row0 < NNODES) {
                __half2 h2 = __floats2half2_rn(acc[mt][nt][0] + b10, acc[mt][nt][1] + b11);
                *(__half2*)(yout + (size_t)row0 * HIDN + colb) = h2;
            }
            if (row0 + 8 < NNODES) {
                __half2 h2 = __floats2half2_rn(acc[mt][nt][2] + b10, acc[mt][nt][3] + b11);
                *(__half2*)(yout + (size_t)(row0 + 8) * HIDN + colb) = h2;
            }
        }
    }
}

// ---------------- edge epilogue v2: 16 lanes/edge, 2 edges/warp-step, f32x2 ----------------
__global__ __launch_bounds__(NTH, 2)
void edge_out(const int* __restrict__ src,
              const int* __restrict__ dst,
              const float* __restrict__ W3,
              const float* __restrict__ b3,
              const float* __restrict__ gamma2,
              const float* __restrict__ beta2,
              float* __restrict__ out,
              int E) {
    const int tid  = threadIdx.x;
    const int wid  = tid >> 5;
    const int lane = tid & 31;
    const int es   = lane >> 4;      // edge slot within warp-step (0/1)
    const int cg   = lane & 15;      // column group (16 cols each)
    const int wbase = blockIdx.x * 512 + wid * 64;
    if (wbase >= E) return;
    const int j0 = cg * 16;

    // per-lane params: gamma/beta packed f32x2, W3 scalar
    unsigned long long gp[8], bp[8];
    float w3s[16];
    #pragma unroll
    for (int i = 0; i < 8; ++i) {
        float2 g = *(const float2*)(gamma2 + j0 + 2 * i);
        float2 b = *(const float2*)(beta2 + j0 + 2 * i);
        gp[i] = pk2(g.x, g.y);
        bp[i] = pk2(b.x, b.y);
    }
    #pragma unroll
    for (int i = 0; i < 16; ++i) w3s[i] = W3[j0 + i];
    const float b3v = b3[0];

    // prefetch step 0
    int eid0 = wbase + es;
    int eidc = (eid0 < E) ? eid0 : (E - 1);
    {
        int se = src[eidc], de = dst[eidc];
        (void)se; (void)de;
    }
    const __half* ps0 = g_ys + (size_t)src[eidc] * HIDN + j0;
    const __half* pd0 = g_yd + (size_t)dst[eidc] * HIDN + j0;
    uint4 us0 = *(const uint4*)ps0, us1 = *(const uint4*)(ps0 + 8);
    uint4 ud0 = *(const uint4*)pd0, ud1 = *(const uint4*)(pd0 + 8);

    #pragma unroll 2
    for (int t = 0; t < 32; ++t) {
        uint4 nus0 = us0, nus1 = us1, nud0 = ud0, nud1 = ud1;
        if (t < 31) {
            int e2 = wbase + 2 * (t + 1) + es;
            if (e2 >= E) e2 = E - 1;
            const __half* ps = g_ys + (size_t)src[e2] * HIDN + j0;
            const __half* pd = g_yd + (size_t)dst[e2] * HIDN + j0;
            nus0 = *(const uint4*)ps;  nus1 = *(const uint4*)(ps + 8);
            nud0 = *(const uint4*)pd;  nud1 = *(const uint4*)(pd + 8);
        }

        // x = ys + yd (fp16 add, convert, pack f32x2)
        unsigned long long xp[8];
        {
            const __half2* a0 = (const __half2*)&us0;
            const __half2* b0 = (const __half2*)&ud0;
            const __half2* a1 = (const __half2*)&us1;
            const __half2* b1p = (const __half2*)&ud1;
            #pragma unroll
            for (int w = 0; w < 4; ++w) {
                float2 f0 = __half22float2(__hadd2(a0[w], b0[w]));
                float2 f1 = __half22float2(__hadd2(a1[w], b1p[w]));
                xp[w]     = pk2(f0.x, f0.y);
                xp[4 + w] = pk2(f1.x, f1.y);
            }
        }

        // stats (packed)
        unsigned long long sum2 = pk2(0.f, 0.f), sq2 = pk2(0.f, 0.f);
        #pragma unroll
        for (int i = 0; i < 8; ++i) {
            sum2 = addx2(sum2, xp[i]);
            sq2  = fmax2(xp[i], xp[i], sq2);
        }
        float sa, sb, qa, qb;
        upk2(sa, sb, sum2);
        upk2(qa, qb, sq2);
        float sum = sa + sb, sq = qa + qb;
        #pragma unroll
        for (int off = 8; off > 0; off >>= 1) {
            sum += __shfl_xor_sync(0xffffffffu, sum, off);
            sq  += __shfl_xor_sync(0xffffffffu, sq, off);
        }
        float mu  = sum * (1.f / 256.f);
        float var = sq * (1.f / 256.f) - mu * mu;
        float rsv = rsqrtf(var + 1e-5f);
        unsigned long long nmu2 = pk2(-mu, -mu);
        unsigned long long rs2  = pk2(rsv, rsv);

        // normalize + relu + dot
        float dot = 0.f;
        #pragma unroll
        for (int i = 0; i < 8; ++i) {
            unsigned long long tt = addx2(xp[i], nmu2);
            tt = mulx2(tt, rs2);
            unsigned long long y = fmax2(tt, gp[i], bp[i]);
            float y0, y1;
            upk2(y0, y1, y);
            y0 = fmaxf(y0, 0.f);
            y1 = fmaxf(y1, 0.f);
            dot = fmaf(y0, w3s[2 * i], dot);
            dot = fmaf(y1, w3s[2 * i + 1], dot);
        }
        #pragma unroll
        for (int off = 8; off > 0; off >>= 1)
            dot += __shfl_xor_sync(0xffffffffu, dot, off);

        int ecur = wbase + 2 * t + es;
        if (cg == 0 && ecur < E) out[ecur] = dot + b3v;

        us0 = nus0; us1 = nus1; ud0 = nud0; ud1 = nud1;
    }
}

extern "C" void kernel_launch(void* const* d_in, const int* in_sizes, int n_in,
                              void* d_out, int out_size) {
    const float* h_all  = (const float*)d_in[0];
    const int*   src    = (const int*)  d_in[1];
    const int*   dst    = (const int*)  d_in[2];
    const float* W1     = (const float*)d_in[3];
    const float* b1     = (const float*)d_in[4];
    const float* W3     = (const float*)d_in[5];
    const float* b3     = (const float*)d_in[6];
    const float* gamma2 = (const float*)d_in[7];
    const float* beta2  = (const float*)d_in[8];
    float* out = (float*)d_out;

    const int E = in_sizes[1];

    cudaFuncSetAttribute(node_proj,
                         cudaFuncAttributeMaxDynamicSharedMemorySize, SMEM_TOTAL);

    prep_w1n<<<(2 * HIDN * KNODE + 255) / 256, 256>>>(W1);

    {
        dim3 g((NNODES + TILE_M - 1) / TILE_M, 2);
        node_proj<<<g, NTH, SMEM_TOTAL>>>(h_all, b1);
    }

    int nb2 = (E + 511) / 512;
    edge_out<<<nb2, NTH>>>(src, dst, W3, b3, gamma2, beta2, out, E);
}

// round 15
// speedup vs baseline: 3.2985x; 1.0721x over previous
#include <cuda_runtime.h>
#include <cuda_fp16.h>
#include <cstdint>

// ---------------- problem constants ----------------
#define NNODES 50000
#define DHEAD  64
#define HIDN   256
#define KDIM   512
#define KNODE  256           // per-node feature count (L*D)
#define TILE_M 64            // nodes per CTA (node GEMM)
#define NTH    256
#define NCHUNK 8             // K=256 / 32
#define BCHUNK_HALFS 8192    // 256 n * 32 k
#define ACHUNK_BYTES 4096    // 64 m * 32 k * 2B
#define BCHUNK_BYTES 16384
#define LND    (NNODES * DHEAD)

// ---------------- node-GEMM smem layout (bytes) ----------------
#define SM_B1    0                 // 256 f
#define SM_PART  1024              // 4 x 64 f row-sum partials (1KB)
#define SM_ABUF  2048              // 3 x 4KB ring
#define SM_BBUF  (SM_ABUF + 3 * ACHUNK_BYTES)   // 3 x 16KB ring
#define SMEM_TOTAL (SM_BBUF + 3 * BCHUNK_BYTES) // 63488 -> 2 CTAs/SM

// ---------------- device globals ----------------
__device__ __half g_BpackN[2 * NCHUNK * BCHUNK_HALFS];// 256 KB
__device__ __half g_ys[(size_t)NNODES * HIDN];        // 25.6 MB (includes b1)
__device__ __half g_yd[(size_t)NNODES * HIDN];        // 25.6 MB
__device__ float  g_ss[NNODES];                       // row sums of ys (fp32, incl b1)
__device__ float  g_sd[NNODES];                       // row sums of yd

// ---------------- helpers ----------------
__device__ __forceinline__ uint32_t smem_u32(const void* p) {
    uint32_t a;
    asm("{ .reg .u64 t; cvta.to.shared.u64 t, %1; cvt.u32.u64 %0, t; }" : "=r"(a) : "l"(p));
    return a;
}
__device__ __forceinline__ float tanh_fast(float x) {
    float r;
    asm("tanh.approx.f32 %0, %1;" : "=f"(r) : "f"(x));
    return r;
}
__device__ __forceinline__ void cp16(uint32_t dst, const void* src) {
    asm volatile("cp.async.ca.shared.global [%0], [%1], 16;" :: "r"(dst), "l"(src));
}
__device__ __forceinline__ void cp_commit() {
    asm volatile("cp.async.commit_group;" ::: "memory");
}
template <int N>
__device__ __forceinline__ void cp_wait() {
    asm volatile("cp.async.wait_group %0;" :: "n"(N) : "memory");
}
__device__ __forceinline__ void mma_f16(float* c, const uint4& a, uint32_t b0, uint32_t b1) {
    asm volatile(
        "mma.sync.aligned.m16n8k16.row.col.f32.f16.f16.f32 "
        "{%0,%1,%2,%3}, {%4,%5,%6,%7}, {%8,%9}, {%0,%1,%2,%3};"
        : "+f"(c[0]), "+f"(c[1]), "+f"(c[2]), "+f"(c[3])
        : "r"(a.x), "r"(a.y), "r"(a.z), "r"(a.w), "r"(b0), "r"(b1));
}

// ---------------- prep: W1 src/dst halves -> fragment pack ----------------
__global__ void prep_w1n(const float* __restrict__ W1) {
    int i = blockIdx.x * blockDim.x + threadIdx.x;
    if (i >= 2 * HIDN * KNODE) return;
    int half = i >> 16;
    int r = i & 65535;
    int j = r >> 8;              // output col (W1 row)
    int kp = r & 255;            // k'
    int l = kp >> 6, cc = kp & 63;
    int ksrc = l * 128 + half * 64 + cc;
    int c = kp >> 5, kc = kp & 31;
    int kt = kc >> 4, kk = kc & 15;
    int gg = ((j >> 6) << 3) | ((j >> 3) & 7);
    int lane = ((j & 7) << 2) | ((kk >> 1) & 3);
    int breg = kk >> 3, lo = kk & 1;
    int idx = half * (NCHUNK * BCHUNK_HALFS) + c * BCHUNK_HALFS +
              ((gg * 32 + lane) << 3) + ((kt * 2 + breg) << 1) + lo;
    g_BpackN[idx] = __float2half(W1[j * KDIM + ksrc]);
}

// ---------------- node GEMM: y[half][node, 256] + per-row sums ----------------
__global__ __launch_bounds__(NTH, 2)
void node_proj(const float* __restrict__ h_all, const float* __restrict__ b1) {
    extern __shared__ char smem[];
    const uint32_t sb = smem_u32(smem);

    const int tid  = threadIdx.x;
    const int wid  = tid >> 5;
    const int lane = tid & 31;
    const int mg   = wid >> 2;
    const int ng   = wid & 3;
    const int nb   = blockIdx.x * TILE_M;
    const int half = blockIdx.y;

    float* b1s  = (float*)(smem + SM_B1);
    float* part = (float*)(smem + SM_PART);     // [4][64]
    const __half* Bsrc0 = g_BpackN + (size_t)half * (NCHUNK * BCHUNK_HALFS);

    #pragma unroll
    for (int s = 0; s < 2; ++s) {
        const __half* bsrc = Bsrc0 + s * BCHUNK_HALFS;
        #pragma unroll
        for (int i = 0; i < 4; ++i)
            cp16(sb + SM_BBUF + s * BCHUNK_BYTES + (i * NTH + tid) * 16,
                 bsrc + (i * NTH + tid) * 8);
        cp_commit();
    }
    if (tid < HIDN) b1s[tid] = (half == 0) ? b1[tid] : 0.f;
    __syncthreads();

    const int e0 = tid >> 3;
    const int q  = tid & 7;
    uint32_t aoff[2][2];
    {
        const int mt = (e0 >> 4) & 1;
        const int r  = e0 & 15;
        #pragma unroll
        for (int i = 0; i < 2; ++i)
            #pragma unroll
            for (int p = 0; p < 2; ++p) {
                int kcp = 4 * q + 2 * p;
                int kt = kcp >> 4, kk = kcp & 15;
                int ln = ((r & 7) << 2) | ((kk >> 1) & 3);
                int areg = (r >> 3) | ((kk >> 3) << 1);
                aoff[i][p] = (uint32_t)(((((i * 2 + mt) * 2 + kt) * 32 + ln) * 4 + areg) * 4);
            }
    }
    int nrow[2];
    #pragma unroll
    for (int i = 0; i < 2; ++i) {
        int n = nb + e0 + i * 32;
        nrow[i] = (n < NNODES) ? n : (NNODES - 1);
    }

    float acc[2][8][4];
    #pragma unroll
    for (int mt = 0; mt < 2; ++mt)
        #pragma unroll
        for (int nt = 0; nt < 8; ++nt)
            #pragma unroll
            for (int j = 0; j < 4; ++j) acc[mt][nt][j] = 0.f;

    // producer: gather fp32 + tanh + pack; chunk c: l=c>>1, cc0=(c&1)*32
    uint2 ph[2];
    #pragma unroll
    for (int i = 0; i < 2; ++i) {
        float4 v = *(const float4*)(h_all + (size_t)nrow[i] * DHEAD + q * 4);
        __half2 a = __floats2half2_rn(tanh_fast(v.x * 0.1f), tanh_fast(v.y * 0.1f));
        __half2 b = __floats2half2_rn(tanh_fast(v.z * 0.1f), tanh_fast(v.w * 0.1f));
        ph[i].x = *(uint32_t*)&a;
        ph[i].y = *(uint32_t*)&b;
    }
    #pragma unroll
    for (int i = 0; i < 2; ++i) {
        *(uint32_t*)(smem + SM_ABUF + aoff[i][0]) = ph[i].x;
        *(uint32_t*)(smem + SM_ABUF + aoff[i][1]) = ph[i].y;
    }
    #pragma unroll
    for (int i = 0; i < 2; ++i) {
        float4 v = *(const float4*)(h_all + (size_t)nrow[i] * DHEAD + 32 + q * 4);
        __half2 a = __floats2half2_rn(tanh_fast(v.x * 0.1f), tanh_fast(v.y * 0.1f));
        __half2 b = __floats2half2_rn(tanh_fast(v.z * 0.1f), tanh_fast(v.w * 0.1f));
        ph[i].x = *(uint32_t*)&a;
        ph[i].y = *(uint32_t*)&b;
    }

    #pragma unroll 1
    for (int c = 0; c < NCHUNK; ++c) {
        if (c < NCHUNK - 1) cp_wait<1>(); else cp_wait<0>();
        __syncthreads();

        if (c < NCHUNK - 2) {
            const int s = (c + 2) % 3;
            const __half* bsrc = Bsrc0 + (c + 2) * BCHUNK_HALFS;
            #pragma unroll
            for (int i = 0; i < 4; ++i)
                cp16(sb + SM_BBUF + s * BCHUNK_BYTES + (i * NTH + tid) * 16,
                     bsrc + (i * NTH + tid) * 8);
            cp_commit();
        }
        if (c < NCHUNK - 1) {
            char* ab = smem + SM_ABUF + ((c + 1) % 3) * ACHUNK_BYTES;
            #pragma unroll
            for (int i = 0; i < 2; ++i) {
                *(uint32_t*)(ab + aoff[i][0]) = ph[i].x;
                *(uint32_t*)(ab + aoff[i][1]) = ph[i].y;
            }
        }
        if (c < NCHUNK - 2) {
            const int cn = c + 2;
            const int l = cn >> 1, cc0 = (cn & 1) * 32;
            const float im = 0.1f * (float)(l + 1);
            const float* hb = h_all + (size_t)l * LND + cc0;
            #pragma unroll
            for (int i = 0; i < 2; ++i) {
                float4 v = *(const float4*)(hb + (size_t)nrow[i] * DHEAD + q * 4);
                __half2 a = __floats2half2_rn(tanh_fast(v.x * im), tanh_fast(v.y * im));
                __half2 b = __floats2half2_rn(tanh_fast(v.z * im), tanh_fast(v.w * im));
                ph[i].x = *(uint32_t*)&a;
                ph[i].y = *(uint32_t*)&b;
            }
        }

        {
            const uint4* Ab = (const uint4*)(smem + SM_ABUF + (c % 3) * ACHUNK_BYTES);
            const uint4* Bb = (const uint4*)(smem + SM_BBUF + (c % 3) * BCHUNK_BYTES);
            uint4 aa[2][2];
            #pragma unroll
            for (int mt = 0; mt < 2; ++mt)
                #pragma unroll
                for (int kt = 0; kt < 2; ++kt)
                    aa[mt][kt] = Ab[((mg * 2 + mt) * 2 + kt) * 32 + lane];
            #pragma unroll
            for (int h = 0; h < 2; ++h) {
                uint4 bb[4];
                #pragma unroll
                for (int n4 = 0; n4 < 4; ++n4)
                    bb[n4] = Bb[(ng * 8 + h * 4 + n4) * 32 + lane];
                #pragma unroll
                for (int kt = 0; kt < 2; ++kt)
                    #pragma unroll
                    for (int mt = 0; mt < 2; ++mt)
                        #pragma unroll
                        for (int n4 = 0; n4 < 4; ++n4)
                            mma_f16(acc[mt][h * 4 + n4], aa[mt][kt],
                                    kt ? bb[n4].z : bb[n4].x,
                                    kt ? bb[n4].w : bb[n4].y);
            }
        }
    }

    // ---- epilogue: +b1, fp16 store, and per-row fp32 sums ----
    const int qr = lane >> 2;
    const int ql = lane & 3;
    __half* yout = half ? g_yd : g_ys;
    float rsum[2][2] = {{0.f, 0.f}, {0.f, 0.f}};   // [mt][ro]
    #pragma unroll
    for (int mt = 0; mt < 2; ++mt) {
        int row0 = nb + mg * 32 + mt * 16 + qr;
        #pragma unroll
        for (int nt = 0; nt < 8; ++nt) {
            int colb = ng * 64 + nt * 8 + ql * 2;
            float b10 = b1s[colb], b11 = b1s[colb + 1];
            float v0 = acc[mt][nt][0] + b10, v1 = acc[mt][nt][1] + b11;
            float v2 = acc[mt][nt][2] + b10, v3 = acc[mt][nt][3] + b11;
            rsum[mt][0] += v0 + v1;
            rsum[mt][1] += v2 + v3;
            if (row0 < NNODES)
                *(__half2*)(yout + (size_t)row0 * HIDN + colb) = __floats2half2_rn(v0, v1);
            if (row0 + 8 < NNODES)
                *(__half2*)(yout + (size_t)(row0 + 8) * HIDN + colb) = __floats2half2_rn(v2, v3);
        }
    }
    // reduce over ql (lanes differing in bits 0-1), then across the 4 ng warps via smem
    #pragma unroll
    for (int off = 1; off <= 2; off <<= 1)
        #pragma unroll
        for (int mt = 0; mt < 2; ++mt)
            #pragma unroll
            for (int ro = 0; ro < 2; ++ro)
                rsum[mt][ro] += __shfl_xor_sync(0xffffffffu, rsum[mt][ro], off);
    if (ql == 0) {
        #pragma unroll
        for (int mt = 0; mt < 2; ++mt)
            #pragma unroll
            for (int ro = 0; ro < 2; ++ro) {
                int lr = mg * 32 + mt * 16 + ro * 8 + qr;
                part[ng * 64 + lr] = rsum[mt][ro];
            }
    }
    __syncthreads();
    if (tid < TILE_M) {
        int n = nb + tid;
        if (n < NNODES) {
            float s = part[tid] + part[64 + tid] + part[128 + tid] + part[192 + tid];
            if (half) g_sd[n] = s; else g_ss[n] = s;
        }
    }
}

// ---------------- edge epilogue v3: 32 lanes/edge, precomputed mean ----------------
__global__ __launch_bounds__(NTH)
void edge_out(const int* __restrict__ src,
              const int* __restrict__ dst,
              const float* __restrict__ W3,
              const float* __restrict__ b3,
              const float* __restrict__ gamma2,
              const float* __restrict__ beta2,
              float* __restrict__ out,
              int E) {
    const int tid  = threadIdx.x;
    const int wid  = tid >> 5;
    const int lane = tid & 31;
    const int ebase = blockIdx.x * NTH + wid * 32;
    if (ebase >= E) return;

    const int j0 = lane * 8;
    float4 ga = *(const float4*)(gamma2 + j0), gb = *(const float4*)(gamma2 + j0 + 4);
    float4 ba = *(const float4*)(beta2 + j0),  bb = *(const float4*)(beta2 + j0 + 4);
    float4 wa = *(const float4*)(W3 + j0),     wb = *(const float4*)(W3 + j0 + 4);
    const float g[8]  = {ga.x, ga.y, ga.z, ga.w, gb.x, gb.y, gb.z, gb.w};
    const float be[8] = {ba.x, ba.y, ba.z, ba.w, bb.x, bb.y, bb.z, bb.w};
    const float w3[8] = {wa.x, wa.y, wa.z, wa.w, wb.x, wb.y, wb.z, wb.w};
    const float b3v = b3[0];

    int eg = ebase + lane;
    if (eg >= E) eg = E - 1;
    const int se = src[eg], de = dst[eg];
    const float msum = g_ss[se] + g_sd[de];   // per-lane: Σx for this lane's edge

    int s0 = __shfl_sync(0xffffffffu, se, 0);
    int d0 = __shfl_sync(0xffffffffu, de, 0);
    uint4 us = *(const uint4*)(g_ys + (size_t)s0 * HIDN + j0);
    uint4 ud = *(const uint4*)(g_yd + (size_t)d0 * HIDN + j0);

    #pragma unroll 4
    for (int t = 0; t < 32; ++t) {
        uint4 usn = us, udn = ud;
        if (t < 31) {
            int s2 = __shfl_sync(0xffffffffu, se, t + 1);
            int d2 = __shfl_sync(0xffffffffu, de, t + 1);
            usn = *(const uint4*)(g_ys + (size_t)s2 * HIDN + j0);
            udn = *(const uint4*)(g_yd + (size_t)d2 * HIDN + j0);
        }
        // x = ys + yd (fp16 add), then fp32; accumulate only sumsq
        float x[8];
        float sq = 0.f;
        {
            const __half2* hs = (const __half2*)&us;
            const __half2* hd = (const __half2*)&ud;
            #pragma unroll
            for (int w = 0; w < 4; ++w) {
                float2 f = __half22float2(__hadd2(hs[w], hd[w]));
                x[2 * w] = f.x;
                x[2 * w + 1] = f.y;
                sq = fmaf(f.x, f.x, sq);
                sq = fmaf(f.y, f.y, sq);
            }
        }
        #pragma unroll
        for (int off = 16; off > 0; off >>= 1)
            sq += __shfl_xor_sync(0xffffffffu, sq, off);

        float mu  = __shfl_sync(0xffffffffu, msum, t) * (1.f / 256.f);
        float var = sq * (1.f / 256.f) - mu * mu;
        float rs  = rsqrtf(var + 1e-5f);
        float nmr = -mu * rs;

        float p = 0.f;
        #pragma unroll
        for (int w = 0; w < 8; ++w) {
            float xn = fmaf(x[w], rs, nmr);
            float y  = fmaxf(fmaf(xn, g[w], be[w]), 0.f);
            p = fmaf(y, w3[w], p);
        }
        #pragma unroll
        for (int off = 16; off > 0; off >>= 1)
            p += __shfl_xor_sync(0xffffffffu, p, off);
        if (lane == 0 && ebase + t < E)
            out[ebase + t] = p + b3v;
        us = usn;
        ud = udn;
    }
}

extern "C" void kernel_launch(void* const* d_in, const int* in_sizes, int n_in,
                              void* d_out, int out_size) {
    const float* h_all  = (const float*)d_in[0];
    const int*   src    = (const int*)  d_in[1];
    const int*   dst    = (const int*)  d_in[2];
    const float* W1     = (const float*)d_in[3];
    const float* b1     = (const float*)d_in[4];
    const float* W3     = (const float*)d_in[5];
    const float* b3     = (const float*)d_in[6];
    const float* gamma2 = (const float*)d_in[7];
    const float* beta2  = (const float*)d_in[8];
    float* out = (float*)d_out;

    const int E = in_sizes[1];

    cudaFuncSetAttribute(node_proj,
                         cudaFuncAttributeMaxDynamicSharedMemorySize, SMEM_TOTAL);

    prep_w1n<<<(2 * HIDN * KNODE + 255) / 256, 256>>>(W1);

    {
        dim3 g((NNODES + TILE_M - 1) / TILE_M, 2);
        node_proj<<<g, NTH, SMEM_TOTAL>>>(h_all, b1);
    }

    int nb2 = (E + NTH - 1) / NTH;
    edge_out<<<nb2, NTH>>>(src, dst, W3, b3, gamma2, beta2, out, E);
}

// round 17
// speedup vs baseline: 3.4432x; 1.0439x over previous
#include <cuda_runtime.h>
#include <cuda_fp16.h>
#include <cstdint>

// ---------------- problem constants ----------------
#define NNODES 50000
#define DHEAD  64
#define HIDN   256
#define KDIM   512
#define KNODE  256           // per-node feature count (L*D)
#define TILE_M 64            // nodes per CTA (node GEMM)
#define NTH    256
#define NCHUNK 8             // K=256 / 32 (per half)
#define NCHUNK2 16           // both halves
#define BCHUNK_HALFS 8192    // 256 n * 32 k
#define ACHUNK_BYTES 4096    // 64 m * 32 k * 2B
#define BCHUNK_BYTES 16384
#define LND    (NNODES * DHEAD)

// ---------------- node-GEMM smem layout (bytes) ----------------
#define SM_B1    0                 // 256 f
#define SM_PART  1024              // 4 x 64 f row-sum partials
#define SM_ABUF  2048              // 8 x 4KB persistent A (32KB)
#define SM_BBUF  (SM_ABUF + 8 * ACHUNK_BYTES)   // 3 x 16KB ring
#define SMEM_TOTAL (SM_BBUF + 3 * BCHUNK_BYTES) // 83968 -> 2 CTAs/SM

// ---------------- device globals ----------------
__device__ __half g_BpackN[2 * NCHUNK * BCHUNK_HALFS];// 256 KB  [half][chunk] = linear in global chunk
__device__ __half g_ys[(size_t)NNODES * HIDN];        // 25.6 MB (includes b1)
__device__ __half g_yd[(size_t)NNODES * HIDN];        // 25.6 MB
__device__ float  g_ss[NNODES];                       // row sums of ys (fp32, incl b1)
__device__ float  g_sd[NNODES];                       // row sums of yd

// ---------------- helpers ----------------
__device__ __forceinline__ uint32_t smem_u32(const void* p) {
    uint32_t a;
    asm("{ .reg .u64 t; cvta.to.shared.u64 t, %1; cvt.u32.u64 %0, t; }" : "=r"(a) : "l"(p));
    return a;
}
__device__ __forceinline__ float tanh_fast(float x) {
    float r;
    asm("tanh.approx.f32 %0, %1;" : "=f"(r) : "f"(x));
    return r;
}
__device__ __forceinline__ void cp16(uint32_t dst, const void* src) {
    asm volatile("cp.async.ca.shared.global [%0], [%1], 16;" :: "r"(dst), "l"(src));
}
__device__ __forceinline__ void cp_commit() {
    asm volatile("cp.async.commit_group;" ::: "memory");
}
template <int N>
__device__ __forceinline__ void cp_wait() {
    asm volatile("cp.async.wait_group %0;" :: "n"(N) : "memory");
}
__device__ __forceinline__ void mma_f16(float* c, const uint4& a, uint32_t b0, uint32_t b1) {
    asm volatile(
        "mma.sync.aligned.m16n8k16.row.col.f32.f16.f16.f32 "
        "{%0,%1,%2,%3}, {%4,%5,%6,%7}, {%8,%9}, {%0,%1,%2,%3};"
        : "+f"(c[0]), "+f"(c[1]), "+f"(c[2]), "+f"(c[3])
        : "r"(a.x), "r"(a.y), "r"(a.z), "r"(a.w), "r"(b0), "r"(b1));
}

// ---------------- prep: W1 src/dst halves -> fragment pack ----------------
__global__ void prep_w1n(const float* __restrict__ W1) {
    int i = blockIdx.x * blockDim.x + threadIdx.x;
    if (i >= 2 * HIDN * KNODE) return;
    int half = i >> 16;
    int r = i & 65535;
    int j = r >> 8;              // output col (W1 row)
    int kp = r & 255;            // k'
    int l = kp >> 6, cc = kp & 63;
    int ksrc = l * 128 + half * 64 + cc;
    int c = kp >> 5, kc = kp & 31;
    int kt = kc >> 4, kk = kc & 15;
    int gg = ((j >> 6) << 3) | ((j >> 3) & 7);
    int lane = ((j & 7) << 2) | ((kk >> 1) & 3);
    int breg = kk >> 3, lo = kk & 1;
    int idx = half * (NCHUNK * BCHUNK_HALFS) + c * BCHUNK_HALFS +
              ((gg * 32 + lane) << 3) + ((kt * 2 + breg) << 1) + lo;
    g_BpackN[idx] = __float2half(W1[j * KDIM + ksrc]);
}

// ---------------- node GEMM (merged halves): ys & yd for 64 nodes/CTA ----------------
__global__ __launch_bounds__(NTH, 2)
void node_proj(const float* __restrict__ h_all, const float* __restrict__ b1) {
    extern __shared__ char smem[];
    const uint32_t sb = smem_u32(smem);

    const int tid  = threadIdx.x;
    const int wid  = tid >> 5;
    const int lane = tid & 31;
    const int mg   = wid >> 2;
    const int ng   = wid & 3;
    const int nb   = blockIdx.x * TILE_M;

    float* b1s  = (float*)(smem + SM_B1);
    float* part = (float*)(smem + SM_PART);     // [4][64]

    // B stages 0,1 (global chunks 0,1) in flight ASAP
    #pragma unroll
    for (int s = 0; s < 2; ++s) {
        const __half* bsrc = g_BpackN + s * BCHUNK_HALFS;
        #pragma unroll
        for (int i = 0; i < 4; ++i)
            cp16(sb + SM_BBUF + s * BCHUNK_BYTES + (i * NTH + tid) * 16,
                 bsrc + (i * NTH + tid) * 8);
        cp_commit();
    }
    if (tid < HIDN) b1s[tid] = b1[tid];
    __syncthreads();

    const int e0 = tid >> 3;
    const int q  = tid & 7;
    uint32_t aoff[2][2];
    {
        const int mt = (e0 >> 4) & 1;
        const int r  = e0 & 15;
        #pragma unroll
        for (int i = 0; i < 2; ++i)
            #pragma unroll
            for (int p = 0; p < 2; ++p) {
                int kcp = 4 * q + 2 * p;
                int kt = kcp >> 4, kk = kcp & 15;
                int ln = ((r & 7) << 2) | ((kk >> 1) & 3);
                int areg = (r >> 3) | ((kk >> 3) << 1);
                aoff[i][p] = (uint32_t)(((((i * 2 + mt) * 2 + kt) * 32 + ln) * 4 + areg) * 4);
            }
    }
    int nrow[2];
    #pragma unroll
    for (int i = 0; i < 2; ++i) {
        int n = nb + e0 + i * 32;
        nrow[i] = (n < NNODES) ? n : (NNODES - 1);
    }

    float acc[2][8][4];
    #pragma unroll
    for (int mt = 0; mt < 2; ++mt)
        #pragma unroll
        for (int nt = 0; nt < 8; ++nt)
            #pragma unroll
            for (int j = 0; j < 4; ++j) acc[mt][nt][j] = 0.f;

    // producer: chunk c (<8): l=c>>1, cc0=(c&1)*32. Gather chunk0 -> STS slot0; gather chunk1 -> ph.
    uint2 ph[2];
    #pragma unroll
    for (int i = 0; i < 2; ++i) {
        float4 v = *(const float4*)(h_all + (size_t)nrow[i] * DHEAD + q * 4);
        __half2 a = __floats2half2_rn(tanh_fast(v.x * 0.1f), tanh_fast(v.y * 0.1f));
        __half2 b = __floats2half2_rn(tanh_fast(v.z * 0.1f), tanh_fast(v.w * 0.1f));
        ph[i].x = *(uint32_t*)&a;
        ph[i].y = *(uint32_t*)&b;
    }
    #pragma unroll
    for (int i = 0; i < 2; ++i) {
        *(uint32_t*)(smem + SM_ABUF + aoff[i][0]) = ph[i].x;
        *(uint32_t*)(smem + SM_ABUF + aoff[i][1]) = ph[i].y;
    }
    #pragma unroll
    for (int i = 0; i < 2; ++i) {
        float4 v = *(const float4*)(h_all + (size_t)nrow[i] * DHEAD + 32 + q * 4);
        __half2 a = __floats2half2_rn(tanh_fast(v.x * 0.1f), tanh_fast(v.y * 0.1f));
        __half2 b = __floats2half2_rn(tanh_fast(v.z * 0.1f), tanh_fast(v.w * 0.1f));
        ph[i].x = *(uint32_t*)&a;
        ph[i].y = *(uint32_t*)&b;
    }

    const int qr = lane >> 2;
    const int ql = lane & 3;

    #pragma unroll 1
    for (int c = 0; c < NCHUNK2; ++c) {
        if (c < NCHUNK2 - 1) cp_wait<1>(); else cp_wait<0>();
        __syncthreads();

        // issue B(c+2) into ring slot (c+2)%3
        if (c < NCHUNK2 - 2) {
            const int s = (c + 2) % 3;
            const __half* bsrc = g_BpackN + (c + 2) * BCHUNK_HALFS;
            #pragma unroll
            for (int i = 0; i < 4; ++i)
                cp16(sb + SM_BBUF + s * BCHUNK_BYTES + (i * NTH + tid) * 16,
                     bsrc + (i * NTH + tid) * 8);
            cp_commit();
        }

        // A production only during half 0 (slots persist for half 1)
        if (c < NCHUNK - 1) {
            char* ab = smem + SM_ABUF + (c + 1) * ACHUNK_BYTES;
            #pragma unroll
            for (int i = 0; i < 2; ++i) {
                *(uint32_t*)(ab + aoff[i][0]) = ph[i].x;
                *(uint32_t*)(ab + aoff[i][1]) = ph[i].y;
            }
        }
        if (c < NCHUNK - 2) {
            const int cn = c + 2;
            const int l = cn >> 1, cc0 = (cn & 1) * 32;
            const float im = 0.1f * (float)(l + 1);
            const float* hb = h_all + (size_t)l * LND + cc0;
            #pragma unroll
            for (int i = 0; i < 2; ++i) {
                float4 v = *(const float4*)(hb + (size_t)nrow[i] * DHEAD + q * 4);
                __half2 a = __floats2half2_rn(tanh_fast(v.x * im), tanh_fast(v.y * im));
                __half2 b = __floats2half2_rn(tanh_fast(v.z * im), tanh_fast(v.w * im));
                ph[i].x = *(uint32_t*)&a;
                ph[i].y = *(uint32_t*)&b;
            }
        }

        // ---- MMA on global chunk c: A slot (c&7), B ring slot (c%3) ----
        {
            const uint4* Ab = (const uint4*)(smem + SM_ABUF + (c & 7) * ACHUNK_BYTES);
            const uint4* Bb = (const uint4*)(smem + SM_BBUF + (c % 3) * BCHUNK_BYTES);
            uint4 aa[2][2];
            #pragma unroll
            for (int mt = 0; mt < 2; ++mt)
                #pragma unroll
                for (int kt = 0; kt < 2; ++kt)
                    aa[mt][kt] = Ab[((mg * 2 + mt) * 2 + kt) * 32 + lane];
            #pragma unroll
            for (int h = 0; h < 2; ++h) {
                uint4 bb[4];
                #pragma unroll
                for (int n4 = 0; n4 < 4; ++n4)
                    bb[n4] = Bb[(ng * 8 + h * 4 + n4) * 32 + lane];
                #pragma unroll
                for (int kt = 0; kt < 2; ++kt)
                    #pragma unroll
                    for (int mt = 0; mt < 2; ++mt)
                        #pragma unroll
                        for (int n4 = 0; n4 < 4; ++n4)
                            mma_f16(acc[mt][h * 4 + n4], aa[mt][kt],
                                    kt ? bb[n4].z : bb[n4].x,
                                    kt ? bb[n4].w : bb[n4].y);
            }
        }

        // ---- epilogue at end of each half ----
        if (c == NCHUNK - 1 || c == NCHUNK2 - 1) {
            const int half = (c == NCHUNK2 - 1);
            __half* yout = half ? g_yd : g_ys;
            float rsum[2][2] = {{0.f, 0.f}, {0.f, 0.f}};
            #pragma unroll
            for (int mt = 0; mt < 2; ++mt) {
                int row0 = nb + mg * 32 + mt * 16 + qr;
                #pragma unroll
                for (int nt = 0; nt < 8; ++nt) {
                    int colb = ng * 64 + nt * 8 + ql * 2;
                    float b10 = half ? 0.f : b1s[colb];
                    float b11 = half ? 0.f : b1s[colb + 1];
                    float v0 = acc[mt][nt][0] + b10, v1 = acc[mt][nt][1] + b11;
                    float v2 = acc[mt][nt][2] + b10, v3 = acc[mt][nt][3] + b11;
                    rsum[mt][0] += v0 + v1;
                    rsum[mt][1] += v2 + v3;
                    if (row0 < NNODES)
                        *(__half2*)(yout + (size_t)row0 * HIDN + colb) = __floats2half2_rn(v0, v1);
                    if (row0 + 8 < NNODES)
                        *(__half2*)(yout + (size_t)(row0 + 8) * HIDN + colb) = __floats2half2_rn(v2, v3);
                    // re-zero acc for half 1
                    acc[mt][nt][0] = 0.f; acc[mt][nt][1] = 0.f;
                    acc[mt][nt][2] = 0.f; acc[mt][nt][3] = 0.f;
                }
            }
            #pragma unroll
            for (int off = 1; off <= 2; off <<= 1)
                #pragma unroll
                for (int mt = 0; mt < 2; ++mt)
                    #pragma unroll
                    for (int ro = 0; ro < 2; ++ro)
                        rsum[mt][ro] += __shfl_xor_sync(0xffffffffu, rsum[mt][ro], off);
            if (ql == 0) {
                #pragma unroll
                for (int mt = 0; mt < 2; ++mt)
                    #pragma unroll
                    for (int ro = 0; ro < 2; ++ro) {
                        int lr = mg * 32 + mt * 16 + ro * 8 + qr;
                        part[ng * 64 + lr] = rsum[mt][ro];
                    }
            }
            __syncthreads();
            if (tid < TILE_M) {
                int n = nb + tid;
                if (n < NNODES) {
                    float s = part[tid] + part[64 + tid] + part[128 + tid] + part[192 + tid];
                    if (half) g_sd[n] = s; else g_ss[n] = s;
                }
            }
        }
    }
}

// ---------------- edge epilogue: 32 lanes/edge, precomputed mean ----------------
__global__ __launch_bounds__(NTH)
void edge_out(const int* __restrict__ src,
              const int* __restrict__ dst,
              const float* __restrict__ W3,
              const float* __restrict__ b3,
              const float* __restrict__ gamma2,
              const float* __restrict__ beta2,
              float* __restrict__ out,
              int E) {
    const int tid  = threadIdx.x;
    const int wid  = tid >> 5;
    const int lane = tid & 31;
    const int ebase = blockIdx.x * NTH + wid * 32;
    if (ebase >= E) return;

    const int j0 = lane * 8;
    float4 ga = *(const float4*)(gamma2 + j0), gb = *(const float4*)(gamma2 + j0 + 4);
    float4 ba = *(const float4*)(beta2 + j0),  bb = *(const float4*)(beta2 + j0 + 4);
    float4 wa = *(const float4*)(W3 + j0),     wb = *(const float4*)(W3 + j0 + 4);
    const float g[8]  = {ga.x, ga.y, ga.z, ga.w, gb.x, gb.y, gb.z, gb.w};
    const float be[8] = {ba.x, ba.y, ba.z, ba.w, bb.x, bb.y, bb.z, bb.w};
    const float w3[8] = {wa.x, wa.y, wa.z, wa.w, wb.x, wb.y, wb.z, wb.w};
    const float b3v = b3[0];

    int eg = ebase + lane;
    if (eg >= E) eg = E - 1;
    const int se = src[eg], de = dst[eg];
    const float msum = g_ss[se] + g_sd[de];   // Σx for this lane's edge

    int s0 = __shfl_sync(0xffffffffu, se, 0);
    int d0 = __shfl_sync(0xffffffffu, de, 0);
    uint4 us = *(const uint4*)(g_ys + (size_t)s0 * HIDN + j0);
    uint4 ud = *(const uint4*)(g_yd + (size_t)d0 * HIDN + j0);

    #pragma unroll 4
    for (int t = 0; t < 32; ++t) {
        uint4 usn = us, udn = ud;
        if (t < 31) {
            int s2 = __shfl_sync(0xffffffffu, se, t + 1);
            int d2 = __shfl_sync(0xffffffffu, de, t + 1);
            usn = *(const uint4*)(g_ys + (size_t)s2 * HIDN + j0);
            udn = *(const uint4*)(g_yd + (size_t)d2 * HIDN + j0);
        }
        float x[8];
        float sq = 0.f;
        {
            const __half2* hs = (const __half2*)&us;
            const __half2* hd = (const __half2*)&ud;
            #pragma unroll
            for (int w = 0; w < 4; ++w) {
                float2 f = __half22float2(__hadd2(hs[w], hd[w]));
                x[2 * w] = f.x;
                x[2 * w + 1] = f.y;
                sq = fmaf(f.x, f.x, sq);
                sq = fmaf(f.y, f.y, sq);
            }
        }
        #pragma unroll
        for (int off = 16; off > 0; off >>= 1)
            sq += __shfl_xor_sync(0xffffffffu, sq, off);

        float mu  = __shfl_sync(0xffffffffu, msum, t) * (1.f / 256.f);
        float var = sq * (1.f / 256.f) - mu * mu;
        float rs  = rsqrtf(var + 1e-5f);
        float nmr = -mu * rs;

        float p = 0.f;
        #pragma unroll
        for (int w = 0; w < 8; ++w) {
            float xn = fmaf(x[w], rs, nmr);
            float y  = fmaxf(fmaf(xn, g[w], be[w]), 0.f);
            p = fmaf(y, w3[w], p);
        }
        #pragma unroll
        for (int off = 16; off > 0; off >>= 1)
            p += __shfl_xor_sync(0xffffffffu, p, off);
        if (lane == 0 && ebase + t < E)
            out[ebase + t] = p + b3v;
        us = usn;
        ud = udn;
    }
}

extern "C" void kernel_launch(void* const* d_in, const int* in_sizes, int n_in,
                              void* d_out, int out_size) {
    const float* h_all  = (const float*)d_in[0];
    const int*   src    = (const int*)  d_in[1];
    const int*   dst    = (const int*)  d_in[2];
    const float* W1     = (const float*)d_in[3];
    const float* b1     = (const float*)d_in[4];
    const float* W3     = (const float*)d_in[5];
    const float* b3     = (const float*)d_in[6];
    const float* gamma2 = (const float*)d_in[7];
    const float* beta2  = (const float*)d_in[8];
    float* out = (float*)d_out;

    const int E = in_sizes[1];

    cudaFuncSetAttribute(node_proj,
                         cudaFuncAttributeMaxDynamicSharedMemorySize, SMEM_TOTAL);

    prep_w1n<<<(2 * HIDN * KNODE + 255) / 256, 256>>>(W1);

    node_proj<<<(NNODES + TILE_M - 1) / TILE_M, NTH, SMEM_TOTAL>>>(h_all, b1);

    int nb2 = (E + NTH - 1) / NTH;
    edge_out<<<nb2, NTH>>>(src, dst, W3, b3, gamma2, beta2, out, E);
}